// round 15
// baseline (speedup 1.0000x reference)
#include <cuda_runtime.h>
#include <cuda_fp16.h>

#define N_NODES 50000
#define N_EDGES 800000
#define D_IN    128
#define D_SH    16
#define D_OUT   128
#define N_PATHS 64
#define SCAN_NB ((N_NODES + 255) / 256)              // 196
#define HIST_NB ((N_EDGES + 255) / 256)              // 3125
#define XK_NB   ((N_NODES * 32 + 255) / 256)         // 6250 (half2 pairs)

// ---- static scratch (no allocations allowed) ----
// INVARIANTS at kernel_launch entry (zero-init at load, re-established each run):
//   d_cnt all zero (scan kernel zeroes after read)
//   d_total == 0   (scatter thread 0 resets it)
__device__ int     d_cnt[N_NODES];
__device__ int     d_start[N_NODES];        // segment begin (permuted placement)
__device__ int     d_stop[N_NODES];         // segment end
__device__ int     d_cursor[N_NODES];
__device__ int     d_total;                 // ticket counter for segment placement
__device__ int     d_srcC[N_EDGES];         // CSR-ordered src node per slot
__device__ __align__(16) __half d_shC[N_EDGES * D_SH];  // CSR-ordered sh rows (fp16)
__device__ __half2 d_XkH[N_NODES * 32];     // XkH[n,q] = (coeff[2q]*x[n,ki[2q]], coeff[2q+1]*x[n,ki[2q+1]])

__device__ __forceinline__ unsigned int h2_bits(__half2 h) {
    __half2_raw r = *reinterpret_cast<__half2_raw*>(&h);
    return (unsigned int)r.x | ((unsigned int)r.y << 16);
}

// ---- fused histogram + Xk(half2) precompute (independent jobs, one grid) ----
__global__ void __launch_bounds__(256)
hist_xk_kernel(const int* __restrict__ dst,
               const float* __restrict__ x,
               const float* __restrict__ coeff,
               const int* __restrict__ ki) {
    int b = blockIdx.x;
    if (b < HIST_NB) {
        int e = b * 256 + threadIdx.x;
        if (e < N_EDGES) atomicAdd(&d_cnt[dst[e]], 1);
    } else {
        int i = (b - HIST_NB) * 256 + threadIdx.x;
        if (i < N_NODES * 32) {
            int n = i >> 5;
            int q = i & 31;
            int ki0 = __ldg(&ki[2 * q]),     ki1 = __ldg(&ki[2 * q + 1]);
            float c0 = __ldg(&coeff[2 * q]), c1 = __ldg(&coeff[2 * q + 1]);
            float f0 = c0 * __ldg(&x[n * D_IN + ki0]);
            float f1 = c1 * __ldg(&x[n * D_IN + ki1]);
            d_XkH[i] = __floats2half2_rn(f0, f1);
        }
    }
}

// ---- single-pass scan: block-local exclusive scan + atomic ticket offset ----
__global__ void __launch_bounds__(256) scan_kernel() {
    __shared__ int wsum[8];
    __shared__ int blk_off;
    int t = threadIdx.x;
    int lane = t & 31, wid = t >> 5;
    int i = blockIdx.x * 256 + t;

    int v = 0;
    if (i < N_NODES) {
        v = d_cnt[i];
        d_cnt[i] = 0;                        // re-establish invariant
    }
    int s = v;
    #pragma unroll
    for (int off = 1; off < 32; off <<= 1) {
        int u = __shfl_up_sync(0xffffffffu, s, off);
        if (lane >= off) s += u;
    }
    if (lane == 31) wsum[wid] = s;
    __syncthreads();
    if (wid == 0) {
        int ws = (lane < 8) ? wsum[lane] : 0;
        #pragma unroll
        for (int off = 1; off < 8; off <<= 1) {
            int u = __shfl_up_sync(0xffffffffu, ws, off);
            if (lane >= off) ws += u;
        }
        if (lane < 8) wsum[lane] = ws;
    }
    __syncthreads();
    int incl = s + (wid > 0 ? wsum[wid - 1] : 0);
    if (t == 0) blk_off = atomicAdd(&d_total, wsum[7]);
    __syncthreads();

    if (i < N_NODES) {
        int b0 = blk_off + incl - v;
        d_start[i]  = b0;
        d_stop[i]   = b0 + v;
        d_cursor[i] = b0;
    }
}

// ---- scatter + sh permute/convert ----
// Reads sh row e fully coalesced (row == thread's own edge), converts to fp16,
// stores 32B to the CSR slot (2 scattered STG.128, fire-and-forget). The random
// side of the sh permutation is now STORES in a latency-slack kernel instead of
// single-touch random DRAM LOADS in spmm.
__global__ void __launch_bounds__(256)
scatter_kernel(const int* __restrict__ src,
               const int* __restrict__ dst,
               const float* __restrict__ sh) {
    int e = blockIdx.x * blockDim.x + threadIdx.x;
    if (e == 0) d_total = 0;                 // reset ticket for next replay
    if (e < N_EDGES) {
        int d = dst[e];
        int pos = atomicAdd(&d_cursor[d], 1);
        d_srcC[pos] = src[e];

        const float4* sh4 = (const float4*)(sh + (size_t)e * D_SH);
        float4 a0 = __ldg(sh4 + 0);
        float4 a1 = __ldg(sh4 + 1);
        float4 a2 = __ldg(sh4 + 2);
        float4 a3 = __ldg(sh4 + 3);
        uint4 w0, w1;
        w0.x = h2_bits(__floats2half2_rn(a0.x, a0.y));
        w0.y = h2_bits(__floats2half2_rn(a0.z, a0.w));
        w0.z = h2_bits(__floats2half2_rn(a1.x, a1.y));
        w0.w = h2_bits(__floats2half2_rn(a1.z, a1.w));
        w1.x = h2_bits(__floats2half2_rn(a2.x, a2.y));
        w1.y = h2_bits(__floats2half2_rn(a2.z, a2.w));
        w1.z = h2_bits(__floats2half2_rn(a3.x, a3.y));
        w1.w = h2_bits(__floats2half2_rn(a3.z, a3.w));
        uint4* dstp = (uint4*)(d_shC + (size_t)pos * D_SH);
        dstp[0] = w0;
        dstp[1] = w1;
    }
}

// One warp per destination node. Lane l owns paths 2l and 2l+1.
// All spmm memory traffic is now streaming (srcC, shC, out) except the XkH
// gather, which is 6.4MB and L2-resident. No random DRAM loads remain.
__global__ void __launch_bounds__(256)
spmm_kernel(const int* __restrict__ kj, const int* __restrict__ ko,
            float* __restrict__ out) {
    __shared__ float buf[8][D_OUT];
    int l = threadIdx.x & 31;
    int w = threadIdx.x >> 5;
    int node = blockIdx.x * 8 + w;
    if (node >= N_NODES) return;

    int kj0 = __ldg(&kj[2 * l]),  kj1 = __ldg(&kj[2 * l + 1]);
    int ko0 = __ldg(&ko[2 * l]),  ko1 = __ldg(&ko[2 * l + 1]);

    float* bf = buf[w];
    bf[l] = 0.f; bf[l + 32] = 0.f; bf[l + 64] = 0.f; bf[l + 96] = 0.f;
    __syncwarp();

    float acc0 = 0.f, acc1 = 0.f;
    int beg = d_start[node];
    int end = d_stop[node];

    int j = beg;
    for (; j + 3 < end; j += 4) {
        // uniform src ids (broadcast loads within one L1 line)
        int s0 = d_srcC[j];
        int s1 = d_srcC[j + 1];
        int s2 = d_srcC[j + 2];
        int s3 = d_srcC[j + 3];
        // issue all loads before consumers
        __half2 h0 = d_XkH[(size_t)s0 * 32 + l];
        __half2 h1 = d_XkH[(size_t)s1 * 32 + l];
        __half2 h2 = d_XkH[(size_t)s2 * 32 + l];
        __half2 h3 = d_XkH[(size_t)s3 * 32 + l];
        const __half* c0 = d_shC + (size_t)(j)     * D_SH;
        const __half* c1 = d_shC + (size_t)(j + 1) * D_SH;
        const __half* c2 = d_shC + (size_t)(j + 2) * D_SH;
        const __half* c3 = d_shC + (size_t)(j + 3) * D_SH;
        float s00 = __half2float(c0[kj0]), s01 = __half2float(c0[kj1]);
        float s10 = __half2float(c1[kj0]), s11 = __half2float(c1[kj1]);
        float s20 = __half2float(c2[kj0]), s21 = __half2float(c2[kj1]);
        float s30 = __half2float(c3[kj0]), s31 = __half2float(c3[kj1]);
        float2 x0 = __half22float2(h0);
        float2 x1 = __half22float2(h1);
        float2 x2 = __half22float2(h2);
        float2 x3 = __half22float2(h3);
        acc0 = fmaf(s00, x0.x, acc0);
        acc1 = fmaf(s01, x0.y, acc1);
        acc0 = fmaf(s10, x1.x, acc0);
        acc1 = fmaf(s11, x1.y, acc1);
        acc0 = fmaf(s20, x2.x, acc0);
        acc1 = fmaf(s21, x2.y, acc1);
        acc0 = fmaf(s30, x3.x, acc0);
        acc1 = fmaf(s31, x3.y, acc1);
    }
    for (; j < end; j++) {
        int s0 = d_srcC[j];
        __half2 h0 = d_XkH[(size_t)s0 * 32 + l];
        const __half* c0 = d_shC + (size_t)j * D_SH;
        float s00 = __half2float(c0[kj0]), s01 = __half2float(c0[kj1]);
        float2 x0 = __half22float2(h0);
        acc0 = fmaf(s00, x0.x, acc0);
        acc1 = fmaf(s01, x0.y, acc1);
    }

    atomicAdd(bf + ko0, acc0);
    atomicAdd(bf + ko1, acc1);
    __syncwarp();

    size_t o = (size_t)node * D_OUT;
    out[o + l]      = bf[l];
    out[o + l + 32] = bf[l + 32];
    out[o + l + 64] = bf[l + 64];
    out[o + l + 96] = bf[l + 96];
}

extern "C" void kernel_launch(void* const* d_in, const int* in_sizes, int n_in,
                              void* d_out, int out_size) {
    const float* x     = (const float*)d_in[0];
    const float* sh    = (const float*)d_in[1];
    const float* coeff = (const float*)d_in[2];
    const int*   src   = (const int*)d_in[3];
    const int*   dst   = (const int*)d_in[4];
    const int*   ki    = (const int*)d_in[5];
    const int*   kj    = (const int*)d_in[6];
    const int*   ko    = (const int*)d_in[7];
    float* out = (float*)d_out;

    hist_xk_kernel<<<HIST_NB + XK_NB, 256>>>(dst, x, coeff, ki);
    scan_kernel<<<SCAN_NB, 256>>>();
    scatter_kernel<<<HIST_NB, 256>>>(src, dst, sh);
    spmm_kernel<<<(N_NODES + 7) / 8, 256>>>(kj, ko, out);
}